// round 13
// baseline (speedup 1.0000x reference)
#include <cuda_runtime.h>
#include <cuda_bf16.h>

// CrossNetwork (DCN-v1): x_{l+1} = input * (x_l . w_l) + x_l + b_l, L=6.
//
// Closed form: x_l = alpha_l*input + y_l,  y_l = sum_{j<l} b_j,
//   p_l = input.w_l, q_l = y_l.w_l,  alpha_{l+1} = alpha_l*(1+p_l)+q_l,
//   out = alpha_L*input + y_L.
// One HBM read + one HBM write of [B,D] (128 MB).
//
// Round 13: 1 row/warp (32-reg input buffer -> fits 3 CTAs/SM = 24 warps),
// warp-autonomous atomic row stealing, zero mainloop barriers, no prefetch.
// 6 warps/SMSP gives full latency coverage of the per-row load batch.

#define D 1024
#define L 6
#define NTHREADS 256
#define D4 (D / 4)          // 256 float4 per row
#define GRID_CTAS 444       // 148 SMs * 3 resident CTAs

__device__ unsigned int g_row_ctr = 0;
__device__ unsigned int g_done_ctr = 0;

__global__ __launch_bounds__(NTHREADS, 3)
void crossnet_kernel(const float* __restrict__ input,
                     const float* __restrict__ Wg,
                     const float* __restrict__ bg,
                     float* __restrict__ out,
                     int B, int totalwarps)
{
    __shared__ float4 w_s[L * D4];   // 24 KB: full W
    __shared__ float4 y_s[D4];       // 4 KB: y_L = sum_l b_l
    __shared__ float  q_s[L];        // 6 scalars

    const int tid  = threadIdx.x;
    const int lane = tid & 31;

    if (tid < L) q_s[tid] = 0.0f;

    // ---- one-time preamble: W -> smem ----
    const float4* W4 = reinterpret_cast<const float4*>(Wg);
    const float4* B4 = reinterpret_cast<const float4*>(bg);
#pragma unroll
    for (int i = 0; i < L; i++)
        w_s[i * D4 + tid] = W4[i * D4 + tid];
    __syncthreads();

    // ---- one-time: y_L and q_l (redundant per CTA; cheap) ----
    {
        float4 y = make_float4(0.f, 0.f, 0.f, 0.f);
        float ql[L];
#pragma unroll
        for (int l = 0; l < L; l++) {
            float4 w  = w_s[l * D4 + tid];
            float4 bb = B4[l * D4 + tid];
            ql[l] = y.x * w.x + y.y * w.y + y.z * w.z + y.w * w.w;
            y.x += bb.x; y.y += bb.y; y.z += bb.z; y.w += bb.w;
        }
        y_s[tid] = y;
#pragma unroll
        for (int l = 0; l < L; l++) {
            float v = ql[l];
#pragma unroll
            for (int o = 16; o > 0; o >>= 1)
                v += __shfl_xor_sync(0xffffffffu, v, o);
            if (lane == 0) atomicAdd(&q_s[l], v);
        }
    }
    __syncthreads();   // w_s, y_s, q_s final; NO barriers after this point

    const float4* inp  = reinterpret_cast<const float4*>(input);
    float4*       outp = reinterpret_cast<float4*>(out);

    // ---- warp-autonomous mainloop: pop single rows ----
    for (;;) {
        unsigned int r = 0;
        if (lane == 0) r = atomicAdd(&g_row_ctr, 1u);
        r = __shfl_sync(0xffffffffu, r, 0);
        if (r >= (unsigned int)B) break;

        const float4* ip = inp + (size_t)r * D4;

        // register-resident input row (HBM/L2 read exactly once)
        float4 in[8];
#pragma unroll
        for (int k = 0; k < 8; k++)
            in[k] = ip[lane + 32 * k];

        float acc[L];
#pragma unroll
        for (int l = 0; l < L; l++) acc[l] = 0.f;

#pragma unroll
        for (int k = 0; k < 8; k++) {
#pragma unroll
            for (int l = 0; l < L; l++) {
                float4 w = w_s[l * D4 + lane + 32 * k];
                acc[l] = fmaf(in[k].x, w.x, acc[l]);
                acc[l] = fmaf(in[k].y, w.y, acc[l]);
                acc[l] = fmaf(in[k].z, w.z, acc[l]);
                acc[l] = fmaf(in[k].w, w.w, acc[l]);
            }
        }

        // butterfly warp reductions -> every lane holds full p_l
#pragma unroll
        for (int l = 0; l < L; l++) {
#pragma unroll
            for (int o = 16; o > 0; o >>= 1)
                acc[l] += __shfl_xor_sync(0xffffffffu, acc[l], o);
        }

        // scalar recurrence: alpha = alpha*(1+p) + q
        float a = 1.0f;
#pragma unroll
        for (int l = 0; l < L; l++)
            a = fmaf(a, acc[l], a) + q_s[l];

        // epilogue: out = alpha * input + y_L (input from registers)
        float4* op = outp + (size_t)r * D4;
#pragma unroll
        for (int k = 0; k < 8; k++) {
            float4 y = y_s[lane + 32 * k];
            float4 rr;
            rr.x = fmaf(a, in[k].x, y.x);
            rr.y = fmaf(a, in[k].y, y.y);
            rr.z = fmaf(a, in[k].z, y.z);
            rr.w = fmaf(a, in[k].w, y.w);
            op[lane + 32 * k] = rr;
        }
    }

    // ---- reset counters for next graph replay (last warp out) ----
    if (lane == 0) {
        __threadfence();
        unsigned int d = atomicAdd(&g_done_ctr, 1u);
        if (d == (unsigned int)totalwarps - 1u) {
            atomicExch(&g_row_ctr, 0u);
            atomicExch(&g_done_ctr, 0u);
        }
    }
}

extern "C" void kernel_launch(void* const* d_in, const int* in_sizes, int n_in,
                              void* d_out, int out_size)
{
    const float* input = (const float*)d_in[0];
    const float* W     = (const float*)d_in[1];
    const float* b     = (const float*)d_in[2];
    float* out         = (float*)d_out;

    const int B    = in_sizes[0] / D;            // 16384
    int grid       = GRID_CTAS;                  // 444
    const int maxg = (B + (NTHREADS / 32) - 1) / (NTHREADS / 32);
    if (grid > maxg) grid = maxg;
    const int totalwarps = grid * (NTHREADS / 32);   // 3552

    crossnet_kernel<<<grid, NTHREADS>>>(input, W, b, out, B, totalwarps);
}